// round 15
// baseline (speedup 1.0000x reference)
#include <cuda_runtime.h>
#include <cstdint>

// Problem constants
#define BB 8
#define NN 4096
#define KK 26
#define DD 64

// Stage-1 tiling: 740 blocks = 148 SMs * occ 5 (single balanced wave).
// Per-batch chunk counts: batches 0-3 get 92 chunks, batches 4-7 get 93.
#define NCHUNK_TOTAL 740
#define KD (KK * DD)               // 1664 floats per n-row of neighbors
#define ROW_BYTES (KD * 4)         // 6656 B
#define TGROW_BYTES (DD * 4)       // 256 B

// Async-pipeline config (3 stages x 2 rows => 41.5 KB static smem)
#define STAGES 3
#define RPS 2
#define NB_STAGE_BYTES (RPS * ROW_BYTES)    // 13312
#define TG_STAGE_BYTES (RPS * TGROW_BYTES)  // 512
#define STAGE_BYTES (NB_STAGE_BYTES + TG_STAGE_BYTES)  // 13824
#define SMEM_DATA (STAGES * STAGE_BYTES)    // 41472

// Deterministic partial-sum scratch: [NCHUNK_TOTAL][K][D] = ~4.9 MB
__device__ float g_partial[NCHUNK_TOTAL * KD];

// batch b owns global chunks [CHUNK_OFF(b), CHUNK_OFF(b) + NCH(b))
__host__ __device__ __forceinline__ int NCH(int b)       { return (b < 4) ? 92 : 93; }
__host__ __device__ __forceinline__ int CHUNK_OFF(int b) { return (b < 4) ? 92 * b : 368 + 93 * (b - 4); }

__device__ __forceinline__ float4 f4_fma(float4 x, float4 m, float4 b) {
    float4 r;
    r.x = fmaf(x.x, m.x, b.x);
    r.y = fmaf(x.y, m.y, b.y);
    r.z = fmaf(x.z, m.z, b.z);
    r.w = fmaf(x.w, m.w, b.w);
    return r;
}
__device__ __forceinline__ float4 f4_scale(float4 x, float s) {
    float4 r; r.x = x.x * s; r.y = x.y * s; r.z = x.z * s; r.w = x.w * s;
    return r;
}
__device__ __forceinline__ void f4_fma_acc(float4& acc, float4 u, float4 v) {
    acc.x = fmaf(u.x, v.x, acc.x);
    acc.y = fmaf(u.y, v.y, acc.y);
    acc.z = fmaf(u.z, v.z, acc.z);
    acc.w = fmaf(u.w, v.w, acc.w);
}
__device__ __forceinline__ void f4_add(float4& acc, float4 u) {
    acc.x += u.x; acc.y += u.y; acc.z += u.z; acc.w += u.w;
}

__device__ __forceinline__ uint32_t smem_u32(const void* p) {
    uint32_t a;
    asm("{ .reg .u64 t; cvta.to.shared.u64 t, %1; cvt.u32.u64 %0, t; }"
        : "=r"(a) : "l"(p));
    return a;
}
__device__ __forceinline__ void mbar_init(uint32_t mbar, uint32_t count) {
    asm volatile("mbarrier.init.shared.b64 [%0], %1;" :: "r"(mbar), "r"(count) : "memory");
}
__device__ __forceinline__ void mbar_expect_tx(uint32_t mbar, uint32_t bytes) {
    asm volatile("mbarrier.arrive.expect_tx.shared.b64 _, [%0], %1;"
                 :: "r"(mbar), "r"(bytes) : "memory");
}
__device__ __forceinline__ void mbar_wait(uint32_t mbar, uint32_t parity) {
    asm volatile(
        "{\n\t"
        ".reg .pred P;\n\t"
        "WAIT_%=:\n\t"
        "mbarrier.try_wait.parity.acquire.cta.shared::cta.b64 P, [%0], %1, 0x989680;\n\t"
        "@!P bra WAIT_%=;\n\t"
        "}"
        :: "r"(mbar), "r"(parity) : "memory");
}
__device__ __forceinline__ void bulk_g2s(uint32_t dst, const void* src,
                                         uint32_t bytes, uint32_t mbar) {
    asm volatile(
        "cp.async.bulk.shared::cta.global.mbarrier::complete_tx::bytes [%0], [%1], %2, [%3];"
        :: "r"(dst), "l"(src), "r"(bytes), "r"(mbar) : "memory");
}

// Stage 1 (R12 config, measured best ~41us): async-bulk pipeline, occ 5.
// 256 threads = 16 d4-lanes x 16 kl-lanes; thread owns k=kl (and kl+16 if <26).
__global__ void __launch_bounds__(256, 5) gat_stage1(
    const float* __restrict__ targets,     // (B,N,D)
    const float* __restrict__ neighbors,   // (B,N,K,D)
    const float* __restrict__ aw,          // (B,N,K)
    const float* __restrict__ kt,          // kernel_target (D)
    const float* __restrict__ bt,          // bias_target   (D)
    const float* __restrict__ kn,          // kernel_neighbor (D)
    const float* __restrict__ bn)          // bias_neighbor   (D)
{
    __shared__ __align__(128) unsigned char smem[SMEM_DATA + STAGES * 8];

    const int gchunk = blockIdx.x;         // 0..739
    int b = (gchunk < 368) ? (gchunk / 92) : (4 + (gchunk - 368) / 93);
    const int chunk = gchunk - CHUNK_OFF(b);
    const int nchunk = NCH(b);

    const int tid   = threadIdx.x;
    const int d4    = tid & 15;
    const int kl    = tid >> 4;
    const bool has_k1 = (kl + 16) < KK;    // kl < 10

    const float4 kt4 = ((const float4*)kt)[d4];
    const float4 bt4 = ((const float4*)bt)[d4];
    const float4 kn4 = ((const float4*)kn)[d4];
    const float4 bn4 = ((const float4*)bn)[d4];

    float4 acc0 = make_float4(0.f, 0.f, 0.f, 0.f);
    float4 acc1 = make_float4(0.f, 0.f, 0.f, 0.f);

    const int n_start = (chunk * NN) / nchunk;
    const int n_end   = ((chunk + 1) * NN) / nchunk;
    const int count   = n_end - n_start;           // 44 or 45
    const int nstg    = (count + RPS - 1) / RPS;

    const long row0 = (long)b * NN + n_start;
    const float* nb_g = neighbors + row0 * (long)KD;
    const float* tg_g = targets   + row0 * DD;
    const float* aw_base = aw + row0 * KK + kl;

    const uint32_t sbase = smem_u32(smem);
    const uint32_t mbar0 = sbase + SMEM_DATA;

    if (tid == 0) {
        #pragma unroll
        for (int s = 0; s < STAGES; s++) mbar_init(mbar0 + s * 8, 1);
    }
    __syncthreads();

    // Prologue: fill the pipeline
    if (tid == 0) {
        #pragma unroll
        for (int i = 0; i < STAGES; i++) {
            if (i < nstg) {
                int rows = min(RPS, count - i * RPS);
                uint32_t nbb = rows * ROW_BYTES;
                uint32_t tgb = rows * TGROW_BYTES;
                uint32_t mb = mbar0 + i * 8;
                mbar_expect_tx(mb, nbb + tgb);
                bulk_g2s(sbase + i * STAGE_BYTES, nb_g + (long)i * RPS * KD, nbb, mb);
                bulk_g2s(sbase + i * STAGE_BYTES + NB_STAGE_BYTES,
                         tg_g + (long)i * RPS * DD, tgb, mb);
            }
        }
    }

    for (int i = 0; i < nstg; i++) {
        const int st = i % STAGES;
        const uint32_t parity = (uint32_t)((i / STAGES) & 1);
        mbar_wait(mbar0 + st * 8, parity);

        const int rows = min(RPS, count - i * RPS);
        const unsigned char* stg = smem + st * STAGE_BYTES;

        #pragma unroll
        for (int r = 0; r < RPS; r++) {
            if (r < rows) {
                const int n = i * RPS + r;
                float4 tg = ((const float4*)(stg + NB_STAGE_BYTES + r * TGROW_BYTES))[d4];
                float4 tt = f4_fma(tg, kn4, bn4);

                float a0 = __ldg(aw_base + (long)n * KK);
                float4 nb0 = ((const float4*)(stg + r * ROW_BYTES + kl * DD * 4))[d4];
                float4 nv0 = f4_fma(nb0, kt4, bt4);
                f4_fma_acc(acc0, nv0, f4_scale(tt, a0));

                if (has_k1) {
                    float a1 = __ldg(aw_base + (long)n * KK + 16);
                    float4 nb1 = ((const float4*)(stg + r * ROW_BYTES + (kl + 16) * DD * 4))[d4];
                    float4 nv1 = f4_fma(nb1, kt4, bt4);
                    f4_fma_acc(acc1, nv1, f4_scale(tt, a1));
                }
            }
        }
        __syncthreads();   // all threads done with stage st

        if (tid == 0 && (i + STAGES) < nstg) {
            int j = i + STAGES;
            int rows2 = min(RPS, count - j * RPS);
            uint32_t nbb = rows2 * ROW_BYTES;
            uint32_t tgb = rows2 * TGROW_BYTES;
            uint32_t mb = mbar0 + st * 8;
            mbar_expect_tx(mb, nbb + tgb);
            bulk_g2s(sbase + st * STAGE_BYTES, nb_g + (long)j * RPS * KD, nbb, mb);
            bulk_g2s(sbase + st * STAGE_BYTES + NB_STAGE_BYTES,
                     tg_g + (long)j * RPS * DD, tgb, mb);
        }
    }

    float* outp = g_partial + (long)gchunk * KD;
    ((float4*)(outp + kl * DD))[d4] = acc0;
    if (has_k1) ((float4*)(outp + (kl + 16) * DD))[d4] = acc1;

    // PDL: make partial stores visible, then allow dependents to launch.
    __threadfence();
    asm volatile("griddepcontrol.launch_dependents;" ::: "memory");
}

// Stage 2: one block per (b, k, d-half). Grid (26, 8, 2) = 416 blocks,
// 128 threads = 8 d4-lanes x 16 chunk-groups. PDL: wait for stage1.
__global__ void __launch_bounds__(128) gat_stage2(float* __restrict__ out)
{
    __shared__ float4 red[16][8];

    // Wait for all stage1 blocks' partial writes (PDL dependency).
    asm volatile("griddepcontrol.wait;" ::: "memory");

    const int k = blockIdx.x;              // 0..KK-1
    const int b = blockIdx.y;              // 0..BB-1
    const int h = blockIdx.z;              // 0..1 (d-half)
    const int tid = threadIdx.x;
    const int d4 = (tid & 7) + h * 8;      // 0..15 within D
    const int g  = tid >> 3;               // 0..15

    const int off = CHUNK_OFF(b);
    const int nchunk = NCH(b);

    const float* base = g_partial + (long)off * KD + (long)k * DD + d4 * 4;
    const long cstride = (long)KD;

    float4 s = make_float4(0.f, 0.f, 0.f, 0.f);
    #pragma unroll
    for (int j = 0; j < 6; j++) {          // ceil(93/16)=6
        int c = g + j * 16;
        if (c < nchunk) {
            float4 v = *(const float4*)(base + (long)c * cstride);
            f4_add(s, v);
        }
    }
    red[g][tid & 7] = s;
    __syncthreads();

    if (tid < 8) {
        float4 S = make_float4(0.f, 0.f, 0.f, 0.f);
        #pragma unroll
        for (int gg = 0; gg < 16; gg++) f4_add(S, red[gg][tid]);

        float4 r;
        r.x = 1.0f / (1.0f + __expf(-S.x));
        r.y = 1.0f / (1.0f + __expf(-S.y));
        r.z = 1.0f / (1.0f + __expf(-S.z));
        r.w = 1.0f / (1.0f + __expf(-S.w));

        ((float4*)(out + ((long)b * KK + k) * DD))[tid + h * 8] = r;
    }
}

extern "C" void kernel_launch(void* const* d_in, const int* in_sizes, int n_in,
                              void* d_out, int out_size)
{
    const float* targets   = (const float*)d_in[0];
    const float* neighbors = (const float*)d_in[1];
    const float* aw        = (const float*)d_in[2];
    const float* kt        = (const float*)d_in[3];
    const float* bt        = (const float*)d_in[4];
    const float* kn        = (const float*)d_in[5];
    const float* bn        = (const float*)d_in[6];
    float* out             = (float*)d_out;

    (void)in_sizes; (void)n_in; (void)out_size;

    gat_stage1<<<NCHUNK_TOTAL, 256>>>(targets, neighbors, aw, kt, bt, kn, bn);

    // Stage 2 with Programmatic Dependent Launch: overlaps its launch latency
    // with stage1's tail; griddepcontrol.wait provides the data dependency.
    cudaLaunchAttribute attrs[1];
    attrs[0].id = cudaLaunchAttributeProgrammaticStreamSerialization;
    attrs[0].val.programmaticStreamSerializationAllowed = 1;

    cudaLaunchConfig_t cfg = {};
    cfg.gridDim = dim3(KK, BB, 2);
    cfg.blockDim = dim3(128, 1, 1);
    cfg.dynamicSmemBytes = 0;
    cfg.stream = 0;
    cfg.attrs = attrs;
    cfg.numAttrs = 1;

    cudaLaunchKernelEx(&cfg, gat_stage2, out);
}

// round 16
// speedup vs baseline: 1.0323x; 1.0323x over previous
#include <cuda_runtime.h>
#include <cstdint>

// Problem constants
#define BB 8
#define NN 4096
#define KK 26
#define DD 64

// Stage-1 tiling: 740 blocks = 148 SMs * occ 5 (single balanced wave).
// Per-batch chunk counts: batches 0-3 get 92 chunks, batches 4-7 get 93.
#define NCHUNK_TOTAL 740
#define KD (KK * DD)               // 1664 floats per n-row of neighbors
#define ROW_BYTES (KD * 4)         // 6656 B
#define TGROW_BYTES (DD * 4)       // 256 B

// Async-pipeline config (3 stages x 2 rows => 41.5 KB static smem)
#define STAGES 3
#define RPS 2
#define NB_STAGE_BYTES (RPS * ROW_BYTES)    // 13312
#define TG_STAGE_BYTES (RPS * TGROW_BYTES)  // 512
#define STAGE_BYTES (NB_STAGE_BYTES + TG_STAGE_BYTES)  // 13824
#define SMEM_DATA (STAGES * STAGE_BYTES)    // 41472

// Deterministic partial-sum scratch: [NCHUNK_TOTAL][K][D] = ~4.9 MB
__device__ float g_partial[NCHUNK_TOTAL * KD];

// batch b owns global chunks [CHUNK_OFF(b), CHUNK_OFF(b) + NCH(b))
__host__ __device__ __forceinline__ int NCH(int b)       { return (b < 4) ? 92 : 93; }
__host__ __device__ __forceinline__ int CHUNK_OFF(int b) { return (b < 4) ? 92 * b : 368 + 93 * (b - 4); }

__device__ __forceinline__ float4 f4_fma(float4 x, float4 m, float4 b) {
    float4 r;
    r.x = fmaf(x.x, m.x, b.x);
    r.y = fmaf(x.y, m.y, b.y);
    r.z = fmaf(x.z, m.z, b.z);
    r.w = fmaf(x.w, m.w, b.w);
    return r;
}
__device__ __forceinline__ float4 f4_scale(float4 x, float s) {
    float4 r; r.x = x.x * s; r.y = x.y * s; r.z = x.z * s; r.w = x.w * s;
    return r;
}
__device__ __forceinline__ void f4_fma_acc(float4& acc, float4 u, float4 v) {
    acc.x = fmaf(u.x, v.x, acc.x);
    acc.y = fmaf(u.y, v.y, acc.y);
    acc.z = fmaf(u.z, v.z, acc.z);
    acc.w = fmaf(u.w, v.w, acc.w);
}
__device__ __forceinline__ void f4_add(float4& acc, float4 u) {
    acc.x += u.x; acc.y += u.y; acc.z += u.z; acc.w += u.w;
}

__device__ __forceinline__ uint32_t smem_u32(const void* p) {
    uint32_t a;
    asm("{ .reg .u64 t; cvta.to.shared.u64 t, %1; cvt.u32.u64 %0, t; }"
        : "=r"(a) : "l"(p));
    return a;
}
__device__ __forceinline__ void mbar_init(uint32_t mbar, uint32_t count) {
    asm volatile("mbarrier.init.shared.b64 [%0], %1;" :: "r"(mbar), "r"(count) : "memory");
}
__device__ __forceinline__ void mbar_arrive(uint32_t mbar) {
    asm volatile("mbarrier.arrive.shared.b64 _, [%0];" :: "r"(mbar) : "memory");
}
__device__ __forceinline__ void mbar_expect_tx(uint32_t mbar, uint32_t bytes) {
    asm volatile("mbarrier.arrive.expect_tx.shared.b64 _, [%0], %1;"
                 :: "r"(mbar), "r"(bytes) : "memory");
}
__device__ __forceinline__ void mbar_wait(uint32_t mbar, uint32_t parity) {
    asm volatile(
        "{\n\t"
        ".reg .pred P;\n\t"
        "WAIT_%=:\n\t"
        "mbarrier.try_wait.parity.acquire.cta.shared::cta.b64 P, [%0], %1, 0x989680;\n\t"
        "@!P bra WAIT_%=;\n\t"
        "}"
        :: "r"(mbar), "r"(parity) : "memory");
}
__device__ __forceinline__ void bulk_g2s(uint32_t dst, const void* src,
                                         uint32_t bytes, uint32_t mbar) {
    asm volatile(
        "cp.async.bulk.shared::cta.global.mbarrier::complete_tx::bytes [%0], [%1], %2, [%3];"
        :: "r"(dst), "l"(src), "r"(bytes), "r"(mbar) : "memory");
}

// Stage 1: async-bulk pipeline with full/empty mbarrier ring (no __syncthreads
// in the mainloop). 256 threads = 16 d4-lanes x 16 kl-lanes, occ 5.
__global__ void __launch_bounds__(256, 5) gat_stage1(
    const float* __restrict__ targets,     // (B,N,D)
    const float* __restrict__ neighbors,   // (B,N,K,D)
    const float* __restrict__ aw,          // (B,N,K)
    const float* __restrict__ kt,          // kernel_target (D)
    const float* __restrict__ bt,          // bias_target   (D)
    const float* __restrict__ kn,          // kernel_neighbor (D)
    const float* __restrict__ bn)          // bias_neighbor   (D)
{
    // data | full[STAGES] | empty[STAGES]
    __shared__ __align__(128) unsigned char smem[SMEM_DATA + 2 * STAGES * 8];

    const int gchunk = blockIdx.x;         // 0..739
    int b = (gchunk < 368) ? (gchunk / 92) : (4 + (gchunk - 368) / 93);
    const int chunk = gchunk - CHUNK_OFF(b);
    const int nchunk = NCH(b);

    const int tid   = threadIdx.x;
    const int d4    = tid & 15;
    const int kl    = tid >> 4;
    const bool has_k1 = (kl + 16) < KK;    // kl < 10
    const int lane  = tid & 31;

    const float4 kt4 = ((const float4*)kt)[d4];
    const float4 bt4 = ((const float4*)bt)[d4];
    const float4 kn4 = ((const float4*)kn)[d4];
    const float4 bn4 = ((const float4*)bn)[d4];

    float4 acc0 = make_float4(0.f, 0.f, 0.f, 0.f);
    float4 acc1 = make_float4(0.f, 0.f, 0.f, 0.f);

    const int n_start = (chunk * NN) / nchunk;
    const int n_end   = ((chunk + 1) * NN) / nchunk;
    const int count   = n_end - n_start;           // 44 or 45
    const int nstg    = (count + RPS - 1) / RPS;

    const long row0 = (long)b * NN + n_start;
    const float* nb_g = neighbors + row0 * (long)KD;
    const float* tg_g = targets   + row0 * DD;
    const float* aw_base = aw + row0 * KK + kl;

    const uint32_t sbase  = smem_u32(smem);
    const uint32_t full0  = sbase + SMEM_DATA;
    const uint32_t empty0 = sbase + SMEM_DATA + STAGES * 8;

    if (tid == 0) {
        #pragma unroll
        for (int s = 0; s < STAGES; s++) {
            mbar_init(full0 + s * 8, 1);    // tx-based completion
            mbar_init(empty0 + s * 8, 8);   // one arrive per warp
        }
    }
    __syncthreads();

    // Prologue: fill the pipeline (slots fresh, no empty wait needed)
    if (tid == 0) {
        #pragma unroll
        for (int i = 0; i < STAGES; i++) {
            if (i < nstg) {
                int rows = min(RPS, count - i * RPS);
                uint32_t nbb = rows * ROW_BYTES;
                uint32_t tgb = rows * TGROW_BYTES;
                uint32_t mb = full0 + i * 8;
                mbar_expect_tx(mb, nbb + tgb);
                bulk_g2s(sbase + i * STAGE_BYTES, nb_g + (long)i * RPS * KD, nbb, mb);
                bulk_g2s(sbase + i * STAGE_BYTES + NB_STAGE_BYTES,
                         tg_g + (long)i * RPS * DD, tgb, mb);
            }
        }
    }

    for (int i = 0; i < nstg; i++) {
        const int st = i % STAGES;
        const uint32_t cyc = (uint32_t)(i / STAGES);
        mbar_wait(full0 + st * 8, cyc & 1);

        const int rows = min(RPS, count - i * RPS);
        const unsigned char* stg = smem + st * STAGE_BYTES;

        #pragma unroll
        for (int r = 0; r < RPS; r++) {
            if (r < rows) {
                const int n = i * RPS + r;
                float4 tg = ((const float4*)(stg + NB_STAGE_BYTES + r * TGROW_BYTES))[d4];
                float4 tt = f4_fma(tg, kn4, bn4);

                float a0 = __ldg(aw_base + (long)n * KK);
                float4 nb0 = ((const float4*)(stg + r * ROW_BYTES + kl * DD * 4))[d4];
                float4 nv0 = f4_fma(nb0, kt4, bt4);
                f4_fma_acc(acc0, nv0, f4_scale(tt, a0));

                if (has_k1) {
                    float a1 = __ldg(aw_base + (long)n * KK + 16);
                    float4 nb1 = ((const float4*)(stg + r * ROW_BYTES + (kl + 16) * DD * 4))[d4];
                    float4 nv1 = f4_fma(nb1, kt4, bt4);
                    f4_fma_acc(acc1, nv1, f4_scale(tt, a1));
                }
            }
        }

        // Per-warp arrival on empty[st]; non-producer warps proceed immediately.
        __syncwarp();
        if (lane == 0) mbar_arrive(empty0 + st * 8);

        // Producer: wait until all 8 warps consumed stage st, then refill.
        if (tid == 0 && (i + STAGES) < nstg) {
            mbar_wait(empty0 + st * 8, cyc & 1);   // flip #(cyc+1) => parity cyc&1
            int j = i + STAGES;
            int rows2 = min(RPS, count - j * RPS);
            uint32_t nbb = rows2 * ROW_BYTES;
            uint32_t tgb = rows2 * TGROW_BYTES;
            uint32_t mb = full0 + st * 8;
            mbar_expect_tx(mb, nbb + tgb);
            bulk_g2s(sbase + st * STAGE_BYTES, nb_g + (long)j * RPS * KD, nbb, mb);
            bulk_g2s(sbase + st * STAGE_BYTES + NB_STAGE_BYTES,
                     tg_g + (long)j * RPS * DD, tgb, mb);
        }
    }

    float* outp = g_partial + (long)gchunk * KD;
    ((float4*)(outp + kl * DD))[d4] = acc0;
    if (has_k1) ((float4*)(outp + (kl + 16) * DD))[d4] = acc1;

    // PDL: make partial stores visible, then allow dependents to launch.
    __threadfence();
    asm volatile("griddepcontrol.launch_dependents;" ::: "memory");
}

// Stage 2: one block per (b, k, d-half). Grid (26, 8, 2) = 416 blocks,
// 128 threads = 8 d4-lanes x 16 chunk-groups. PDL: wait for stage1.
__global__ void __launch_bounds__(128) gat_stage2(float* __restrict__ out)
{
    __shared__ float4 red[16][8];

    asm volatile("griddepcontrol.wait;" ::: "memory");

    const int k = blockIdx.x;              // 0..KK-1
    const int b = blockIdx.y;              // 0..BB-1
    const int h = blockIdx.z;              // 0..1 (d-half)
    const int tid = threadIdx.x;
    const int d4 = (tid & 7) + h * 8;      // 0..15 within D
    const int g  = tid >> 3;               // 0..15

    const int off = CHUNK_OFF(b);
    const int nchunk = NCH(b);

    const float* base = g_partial + (long)off * KD + (long)k * DD + d4 * 4;
    const long cstride = (long)KD;

    float4 s = make_float4(0.f, 0.f, 0.f, 0.f);
    #pragma unroll
    for (int j = 0; j < 6; j++) {          // ceil(93/16)=6
        int c = g + j * 16;
        if (c < nchunk) {
            float4 v = *(const float4*)(base + (long)c * cstride);
            f4_add(s, v);
        }
    }
    red[g][tid & 7] = s;
    __syncthreads();

    if (tid < 8) {
        float4 S = make_float4(0.f, 0.f, 0.f, 0.f);
        #pragma unroll
        for (int gg = 0; gg < 16; gg++) f4_add(S, red[gg][tid]);

        float4 r;
        r.x = 1.0f / (1.0f + __expf(-S.x));
        r.y = 1.0f / (1.0f + __expf(-S.y));
        r.z = 1.0f / (1.0f + __expf(-S.z));
        r.w = 1.0f / (1.0f + __expf(-S.w));

        ((float4*)(out + ((long)b * KK + k) * DD))[tid + h * 8] = r;
    }
}

extern "C" void kernel_launch(void* const* d_in, const int* in_sizes, int n_in,
                              void* d_out, int out_size)
{
    const float* targets   = (const float*)d_in[0];
    const float* neighbors = (const float*)d_in[1];
    const float* aw        = (const float*)d_in[2];
    const float* kt        = (const float*)d_in[3];
    const float* bt        = (const float*)d_in[4];
    const float* kn        = (const float*)d_in[5];
    const float* bn        = (const float*)d_in[6];
    float* out             = (float*)d_out;

    (void)in_sizes; (void)n_in; (void)out_size;

    gat_stage1<<<NCHUNK_TOTAL, 256>>>(targets, neighbors, aw, kt, bt, kn, bn);

    cudaLaunchAttribute attrs[1];
    attrs[0].id = cudaLaunchAttributeProgrammaticStreamSerialization;
    attrs[0].val.programmaticStreamSerializationAllowed = 1;

    cudaLaunchConfig_t cfg = {};
    cfg.gridDim = dim3(KK, BB, 2);
    cfg.blockDim = dim3(128, 1, 1);
    cfg.dynamicSmemBytes = 0;
    cfg.stream = 0;
    cfg.attrs = attrs;
    cfg.numAttrs = 1;

    cudaLaunchKernelEx(&cfg, gat_stage2, out);
}